// round 3
// baseline (speedup 1.0000x reference)
#include <cuda_runtime.h>
#include <math.h>

#define BATCH 256
#define TSTEPS 50
#define INSZ 400
#define G4 1024
#define GAMMA 0.95f
#define EPSF 1e-8f

// ---------- device scratch (static: no allocations allowed) ----------
__device__ float g_xw[TSTEPS * BATCH * G4];   // precomputed x@W_ih[0:405] + b  (52.4MB)
__device__ float g_h[BATCH * 256];
__device__ float g_c[BATCH * 256];
__device__ float g_r[BATCH * 256];            // prev reads (flattened [4][64])
__device__ float g_M[BATCH * 256 * 64];       // memory (16.8MB)
__device__ float g_wr[BATCH * 4 * 256];       // read weights
__device__ float g_wu[BATCH * 256];           // usage weights
__device__ float g_p[BATCH * 260];            // key/gate pre-activations

__device__ __forceinline__ float sigf(float x) { return 1.0f / (1.0f + expf(-x)); }

// ---------- init state ----------
__global__ void k_init() {
    int i = blockIdx.x * blockDim.x + threadIdx.x;
    if (i < BATCH * 256 * 64) g_M[i] = 1e-6f;
    if (i < BATCH * 1024) g_wr[i] = 1.0f / 256.0f;
    if (i < BATCH * 256) {
        g_h[i] = 0.0f; g_c[i] = 0.0f; g_r[i] = 0.0f;
        g_wu[i] = 1.0f / 256.0f;
    }
}

// ---------- K1: xw[t][b][:] = [x_t, offset_onehot] @ W_ih[0:405] + b_lstm ----------
// GEMM [12800,400] @ [400,1024]; offset one-hot == row-select of W_ih[400+tgt].
__global__ __launch_bounds__(256) void k1_xw(
    const float* __restrict__ X, const int* __restrict__ tgt,
    const float* __restrict__ Wih, const float* __restrict__ bl)
{
    __shared__ float As[16][68];
    __shared__ float Bs[16][64];
    const int tid = threadIdx.x;
    const int tx = tid & 15, ty = tid >> 4;
    const int m0 = blockIdx.y * 64, n0 = blockIdx.x * 64;
    const int arow = tid >> 2, akq = tid & 3;
    const int bk = tid >> 4, bc = tid & 15;
    float acc[4][4] = {};
    for (int kt = 0; kt < 25; kt++) {
        float4 av = *(const float4*)(X + (size_t)(m0 + arow) * INSZ + kt * 16 + akq * 4);
        As[akq * 4 + 0][arow] = av.x; As[akq * 4 + 1][arow] = av.y;
        As[akq * 4 + 2][arow] = av.z; As[akq * 4 + 3][arow] = av.w;
        *(float4*)&Bs[bk][bc * 4] =
            *(const float4*)(Wih + (size_t)(kt * 16 + bk) * G4 + n0 + bc * 4);
        __syncthreads();
#pragma unroll
        for (int k = 0; k < 16; k++) {
            float4 a = *(float4*)&As[k][ty * 4];
            float4 b = *(float4*)&Bs[k][tx * 4];
            acc[0][0] += a.x * b.x; acc[0][1] += a.x * b.y; acc[0][2] += a.x * b.z; acc[0][3] += a.x * b.w;
            acc[1][0] += a.y * b.x; acc[1][1] += a.y * b.y; acc[1][2] += a.y * b.z; acc[1][3] += a.y * b.w;
            acc[2][0] += a.z * b.x; acc[2][1] += a.z * b.y; acc[2][2] += a.z * b.z; acc[2][3] += a.z * b.w;
            acc[3][0] += a.w * b.x; acc[3][1] += a.w * b.y; acc[3][2] += a.w * b.z; acc[3][3] += a.w * b.w;
        }
        __syncthreads();
    }
#pragma unroll
    for (int i = 0; i < 4; i++) {
        int m = m0 + ty * 4 + i;
        int bb = m / TSTEPS, t = m % TSTEPS;
        const float* offrow = (t > 0) ? (Wih + (size_t)(400 + tgt[m - 1]) * G4) : (const float*)0;
        float* dst = g_xw + ((size_t)t * BATCH + bb) * G4 + n0 + tx * 4;
#pragma unroll
        for (int j = 0; j < 4; j++) {
            int c = n0 + tx * 4 + j;
            float v = acc[i][j] + bl[c];
            if (offrow) v += offrow[c];
            dst[j] = v;
        }
    }
}

// ---------- K2: recurrent GEMM + LSTM fused ----------
__global__ __launch_bounds__(256) void k2_step(
    const float* __restrict__ Wih, const float* __restrict__ Whh, int t)
{
    __shared__ float As[16][34];
    __shared__ float Bs[16][16][4];
    const int tid = threadIdx.x;
    const int tx = tid & 15, ty = tid >> 4;
    const int b0 = blockIdx.x * 32, u0 = blockIdx.y * 16;
    const int arow = tid >> 3, akq = tid & 7;
    const int bk = tid >> 4, bu = tid & 15;
    float acc[2][4] = {};
    for (int kt = 0; kt < 32; kt++) {
        const float* src = (kt < 16) ? g_r : g_h;
        float2 av = *(const float2*)(src + (size_t)(b0 + arow) * 256 + (kt & 15) * 16 + akq * 2);
        As[akq * 2][arow] = av.x; As[akq * 2 + 1][arow] = av.y;
        const float* W = (kt < 16) ? (Wih + (size_t)405 * G4) : Whh;
        int rb = (kt & 15) * 16 + bk;
#pragma unroll
        for (int g = 0; g < 4; g++)
            Bs[bk][bu][g] = W[(size_t)rb * G4 + g * 256 + u0 + bu];
        __syncthreads();
#pragma unroll
        for (int k = 0; k < 16; k++) {
            float a0 = As[k][ty * 2], a1 = As[k][ty * 2 + 1];
            float4 b = *(float4*)&Bs[k][tx][0];
            acc[0][0] += a0 * b.x; acc[0][1] += a0 * b.y; acc[0][2] += a0 * b.z; acc[0][3] += a0 * b.w;
            acc[1][0] += a1 * b.x; acc[1][1] += a1 * b.y; acc[1][2] += a1 * b.z; acc[1][3] += a1 * b.w;
        }
        __syncthreads();
    }
    const int u = u0 + tx;
#pragma unroll
    for (int i = 0; i < 2; i++) {
        int bb = b0 + ty * 2 + i;
        const float* xw = g_xw + ((size_t)t * BATCH + bb) * G4;
        float gi = acc[i][0] + xw[u];
        float gf = acc[i][1] + xw[256 + u];
        float gg = acc[i][2] + xw[512 + u];
        float go = acc[i][3] + xw[768 + u];
        float cc = sigf(gf) * g_c[bb * 256 + u] + sigf(gi) * tanhf(gg);
        float hh = sigf(go) * tanhf(cc);
        g_c[bb * 256 + u] = cc;
        g_h[bb * 256 + u] = hh;
    }
}

// ---------- K3: p = h @ W_kp + b_kp  ([256,256]@[256,260]) ----------
__global__ __launch_bounds__(256) void k3_kp(
    const float* __restrict__ Wkp, const float* __restrict__ bkp)
{
    extern __shared__ float s3[];
    float* hs = s3;              // [32][260]
    float* bsw = s3 + 32 * 260;  // [256][16]
    const int tid = threadIdx.x;
    const int b0 = blockIdx.x * 32, c0 = blockIdx.y * 16;
    for (int e = tid; e < 32 * 64; e += 256) {
        int row = e >> 6, kq = e & 63;
        float4 hv = *(const float4*)(g_h + (size_t)(b0 + row) * 256 + kq * 4);
        float* d = hs + row * 260 + kq * 4;
        d[0] = hv.x; d[1] = hv.y; d[2] = hv.z; d[3] = hv.w;
    }
    for (int e = tid; e < 256 * 16; e += 256) {
        int k = e >> 4, c = e & 15;
        int col = c0 + c;
        bsw[k * 16 + c] = (col < 260) ? Wkp[(size_t)k * 260 + col] : 0.0f;
    }
    __syncthreads();
    const int c = tid & 15, r2 = tid >> 4;
    const int row0 = r2 * 2;
    float a0 = 0.0f, a1 = 0.0f;
#pragma unroll 4
    for (int k = 0; k < 256; k++) {
        float wv = bsw[k * 16 + c];
        a0 += hs[row0 * 260 + k] * wv;
        a1 += hs[(row0 + 1) * 260 + k] * wv;
    }
    int col = c0 + c;
    if (col < 260) {
        g_p[(size_t)(b0 + row0) * 260 + col] = a0 + bkp[col];
        g_p[(size_t)(b0 + row0 + 1) * 260 + col] = a1 + bkp[col];
    }
}

// ---------- K4: memory module + output head (one CTA per batch element) ----------
__global__ __launch_bounds__(256) void k4_mem(
    const float* __restrict__ Wout, const float* __restrict__ bout,
    float* __restrict__ out, int t)
{
    extern __shared__ float sm[];
    float* sM     = sm;              // 256*65 (stride-65 padded)
    float* sk     = sM + 16640;      // 256
    float* ssim   = sk + 256;        // 4*256 (sim -> w_r in place)
    float* sww    = ssim + 1024;     // [n][r] 256*4
    float* swu    = sww + 1024;      // 256
    float* sh     = swu + 256;       // 256
    float* sreads = sh + 256;        // 256
    float* sred   = sreads + 256;    // 256
    float* swp    = sred + 256;      // 40 (warp partials for logits)
    float* sex    = swp + 40;        // 16: [0..3] rk_inv, [4..7] alpha
    int*   sredi  = (int*)(sex + 16);// 256
    int*   slu    = sredi + 256;     // 4

    const int b = blockIdx.x;
    const int tid = threadIdx.x;
    const int lane = tid & 31, wid = tid >> 5;

    // --- loads ---
    sk[tid] = tanhf(g_p[(size_t)b * 260 + tid]);
    if (tid < 4) sex[4 + tid] = sigf(g_p[(size_t)b * 260 + 256 + tid]);
    swu[tid] = g_wu[b * 256 + tid];
    sh[tid]  = g_h[b * 256 + tid];
    {
        const float4* gm = (const float4*)(g_M + (size_t)b * 16384);
#pragma unroll 4
        for (int e = 0; e < 16; e++) {
            float4 v = gm[e * 256 + tid];
            int gidx = (e * 256 + tid) * 4;
            int n = gidx >> 6, d = gidx & 63;
            float* dst = sM + n * 65 + d;
            dst[0] = v.x; dst[1] = v.y; dst[2] = v.z; dst[3] = v.w;
        }
    }
    __syncthreads();

    // --- key inverse norms (warps 0..3) ---
    if (wid < 4) {
        float v0 = sk[wid * 64 + lane], v1 = sk[wid * 64 + lane + 32];
        float s = v0 * v0 + v1 * v1;
#pragma unroll
        for (int o = 16; o > 0; o >>= 1) s += __shfl_xor_sync(0xffffffffu, s, o);
        if (lane == 0) sex[wid] = 1.0f / (sqrtf(s) + EPSF);
    }

    // --- top-4 least-used (ascending value; tie -> lower index, matches lax.top_k) ---
    float myval = swu[tid];
    for (int j = 0; j < 4; j++) {
        sred[tid] = myval; sredi[tid] = tid;
        __syncthreads();
        for (int s = 128; s > 0; s >>= 1) {
            if (tid < s) {
                float ov = sred[tid + s]; int oi = sredi[tid + s];
                float cv = sred[tid];     int ci = sredi[tid];
                if (ov < cv || (ov == cv && oi < ci)) { sred[tid] = ov; sredi[tid] = oi; }
            }
            __syncthreads();
        }
        if (tid == 0) slu[j] = sredi[0];
        __syncthreads();
        if (tid == slu[j]) myval = 3.0e38f;
    }

    // --- write weights w_w[n][r] ---
    {
        float a0 = sex[4], a1 = sex[5], a2 = sex[6], a3 = sex[7];
        const float* wr = g_wr + (size_t)b * 1024;
        float4 w;
        w.x = a0 * wr[tid]       + (1.0f - a0) * ((tid == slu[0]) ? 1.0f : 0.0f);
        w.y = a1 * wr[256 + tid] + (1.0f - a1) * ((tid == slu[1]) ? 1.0f : 0.0f);
        w.z = a2 * wr[512 + tid] + (1.0f - a2) * ((tid == slu[2]) ? 1.0f : 0.0f);
        w.w = a3 * wr[768 + tid] + (1.0f - a3) * ((tid == slu[3]) ? 1.0f : 0.0f);
        *(float4*)&sww[tid * 4] = w;
    }
    __syncthreads();

    // --- erase slot lu0 + additive write; persist M ---
    {
        const int d = tid & 63, nb = tid >> 6;
        const int lu0 = slu[0];
        const float k0 = sk[d], k1 = sk[64 + d], k2 = sk[128 + d], k3 = sk[192 + d];
        float* gm = g_M + (size_t)b * 16384;
#pragma unroll 4
        for (int e = 0; e < 64; e++) {
            int n = e * 4 + nb;
            int sidx = n * 65 + d;
            float4 w = *(float4*)&sww[n * 4];
            float v = (n == lu0) ? 0.0f : sM[sidx];
            v += w.x * k0 + w.y * k1 + w.z * k2 + w.w * k3;
            sM[sidx] = v;
            gm[n * 64 + d] = v;
        }
    }
    __syncthreads();

    // --- row norms + cosine sims (one memory row per thread) ---
    {
        const float* mrow = sM + tid * 65;
        float s = 0, d0 = 0, d1 = 0, d2 = 0, d3 = 0;
#pragma unroll 8
        for (int dd = 0; dd < 64; dd += 4) {
            float4 kk0 = *(const float4*)&sk[dd];
            float4 kk1 = *(const float4*)&sk[64 + dd];
            float4 kk2 = *(const float4*)&sk[128 + dd];
            float4 kk3 = *(const float4*)&sk[192 + dd];
            float m0 = mrow[dd], m1 = mrow[dd + 1], m2 = mrow[dd + 2], m3 = mrow[dd + 3];
            s  += m0 * m0 + m1 * m1 + m2 * m2 + m3 * m3;
            d0 += m0 * kk0.x + m1 * kk0.y + m2 * kk0.z + m3 * kk0.w;
            d1 += m0 * kk1.x + m1 * kk1.y + m2 * kk1.z + m3 * kk1.w;
            d2 += m0 * kk2.x + m1 * kk2.y + m2 * kk2.z + m3 * kk2.w;
            d3 += m0 * kk3.x + m1 * kk3.y + m2 * kk3.z + m3 * kk3.w;
        }
        float inv = 1.0f / (sqrtf(s) + EPSF);
        ssim[tid]       = d0 * inv * sex[0];
        ssim[256 + tid] = d1 * inv * sex[1];
        ssim[512 + tid] = d2 * inv * sex[2];
        ssim[768 + tid] = d3 * inv * sex[3];
    }
    __syncthreads();

    // --- softmax over slots, per read head (64-thread groups) ---
    {
        const int g = tid >> 6, j = tid & 63;
        float* row = ssim + g * 256;
        float v0 = row[j], v1 = row[64 + j], v2 = row[128 + j], v3 = row[192 + j];
        float mx = fmaxf(fmaxf(v0, v1), fmaxf(v2, v3));
        sred[tid] = mx; __syncthreads();
        for (int s = 32; s > 0; s >>= 1) {
            if (j < s) sred[tid] = fmaxf(sred[tid], sred[tid + s]);
            __syncthreads();
        }
        mx = sred[g * 64]; __syncthreads();
        float e0 = expf(v0 - mx), e1 = expf(v1 - mx), e2 = expf(v2 - mx), e3 = expf(v3 - mx);
        sred[tid] = e0 + e1 + e2 + e3; __syncthreads();
        for (int s = 32; s > 0; s >>= 1) {
            if (j < s) sred[tid] += sred[tid + s];
            __syncthreads();
        }
        float inv = 1.0f / sred[g * 64];
        row[j] = e0 * inv; row[64 + j] = e1 * inv; row[128 + j] = e2 * inv; row[192 + j] = e3 * inv;
    }
    __syncthreads();

    // --- usage update + persist w_r ---
    {
        float wrs = ssim[tid] + ssim[256 + tid] + ssim[512 + tid] + ssim[768 + tid];
        float4 w = *(float4*)&sww[tid * 4];
        g_wu[b * 256 + tid] = GAMMA * swu[tid] + wrs + (w.x + w.y + w.z + w.w);
        float* gwr = g_wr + (size_t)b * 1024;
        gwr[tid] = ssim[tid]; gwr[256 + tid] = ssim[256 + tid];
        gwr[512 + tid] = ssim[512 + tid]; gwr[768 + tid] = ssim[768 + tid];
    }
    // --- reads[r][d] = sum_n w_r[r][n] * M[n][d] ---
    {
        const int r = tid >> 6, dd = tid & 63;
        const float* wr = ssim + r * 256;
        float acc = 0.0f;
#pragma unroll 4
        for (int n = 0; n < 256; n += 4) {
            float4 w = *(const float4*)&wr[n];
            acc += w.x * sM[n * 65 + dd] + w.y * sM[(n + 1) * 65 + dd]
                 + w.z * sM[(n + 2) * 65 + dd] + w.w * sM[(n + 3) * 65 + dd];
        }
        sreads[tid] = acc;
        g_r[b * 256 + tid] = acc;
    }
    __syncthreads();

    // --- logits = [h, reads] @ W_out + b_out; softmax -> out[b][t][:] ---
    {
        const float* w1 = Wout + (size_t)tid * 5;
        const float* w2 = Wout + (size_t)(256 + tid) * 5;
        float hv = sh[tid], rv = sreads[tid];
        float p0 = hv * w1[0] + rv * w2[0];
        float p1 = hv * w1[1] + rv * w2[1];
        float p2 = hv * w1[2] + rv * w2[2];
        float p3 = hv * w1[3] + rv * w2[3];
        float p4 = hv * w1[4] + rv * w2[4];
#pragma unroll
        for (int o = 16; o > 0; o >>= 1) {
            p0 += __shfl_xor_sync(0xffffffffu, p0, o);
            p1 += __shfl_xor_sync(0xffffffffu, p1, o);
            p2 += __shfl_xor_sync(0xffffffffu, p2, o);
            p3 += __shfl_xor_sync(0xffffffffu, p3, o);
            p4 += __shfl_xor_sync(0xffffffffu, p4, o);
        }
        if (lane == 0) {
            swp[wid * 5 + 0] = p0; swp[wid * 5 + 1] = p1; swp[wid * 5 + 2] = p2;
            swp[wid * 5 + 3] = p3; swp[wid * 5 + 4] = p4;
        }
        __syncthreads();
        if (tid == 0) {
            float l[5];
#pragma unroll
            for (int c = 0; c < 5; c++) {
                float s = bout[c];
#pragma unroll
                for (int w = 0; w < 8; w++) s += swp[w * 5 + c];
                l[c] = s;
            }
            float mx = l[0];
#pragma unroll
            for (int c = 1; c < 5; c++) mx = fmaxf(mx, l[c]);
            float e[5], s = 0.0f;
#pragma unroll
            for (int c = 0; c < 5; c++) { e[c] = expf(l[c] - mx); s += e[c]; }
            float inv = 1.0f / s;
            float* o = out + ((size_t)b * TSTEPS + t) * 5;
#pragma unroll
            for (int c = 0; c < 5; c++) o[c] = e[c] * inv;
        }
    }
}

// ---------- launch ----------
extern "C" void kernel_launch(void* const* d_in, const int* in_sizes, int n_in,
                              void* d_out, int out_size) {
    const float* X    = (const float*)d_in[0];
    const int*   tgt  = (const int*)d_in[1];
    const float* Wih  = (const float*)d_in[2];
    const float* Whh  = (const float*)d_in[3];
    const float* bl   = (const float*)d_in[4];
    const float* Wkp  = (const float*)d_in[5];
    const float* bkp  = (const float*)d_in[6];
    const float* Wout = (const float*)d_in[7];
    const float* bout = (const float*)d_in[8];
    float* out = (float*)d_out;

    const int smem3 = (32 * 260 + 256 * 16) * 4;           // 49664 B
    const int smem4 = (20024 + 260) * 4;                   // 81136 B
    cudaFuncSetAttribute(k3_kp,  cudaFuncAttributeMaxDynamicSharedMemorySize, smem3);
    cudaFuncSetAttribute(k4_mem, cudaFuncAttributeMaxDynamicSharedMemorySize, smem4);

    k_init<<<16384, 256>>>();
    k1_xw<<<dim3(16, 200), 256>>>(X, tgt, Wih, bl);
    for (int t = 0; t < TSTEPS; t++) {
        k2_step<<<dim3(8, 16), 256>>>(Wih, Whh, t);
        k3_kp<<<dim3(8, 17), 256, smem3>>>(Wkp, bkp);
        k4_mem<<<256, 256, smem4>>>(Wout, bout, out, t);
    }
}